// round 1
// baseline (speedup 1.0000x reference)
#include <cuda_runtime.h>
#include <cstdint>

// Problem dims (fixed): B=4, N=16384 -> 65536 rows, Dn=128, L=256, H=8, DH=32.
// Only the graph hetero branch (T=1) affects the output (loop overwrites `out`).

#define NROWS_TOTAL 65536
#define ROWS_PER_BLK 64
#define THREADS 256
#define SMEM_BYTES 144384  // see layout below (36096 floats)

// Precomputed small tensors (device globals; no runtime alloc allowed)
__device__ float g_Wnq[128 * 256];  // W_node @ Wq
__device__ float g_bnq[256];        // b_node @ Wq + bq
__device__ float g_kvec[256];       // per-head softmaxed k (graph branch)
__device__ float g_U[8 * 256];      // U[h] = v_h @ W_out[h*32:(h+1)*32, :]

// ---------------------------------------------------------------------------
// Precompute 1: graph-branch k (softmaxed), U = v @ W_out slice, fused bias.
// One block of 256 threads; each thread owns output channel j.
// ---------------------------------------------------------------------------
__global__ void precompute1_kernel(
    const float* __restrict__ energy,
    const float* __restrict__ W_graph, const float* __restrict__ b_graph,
    const float* __restrict__ Wq, const float* __restrict__ bq,
    const float* __restrict__ b_node,
    const float* __restrict__ Wk, const float* __restrict__ bk,
    const float* __restrict__ Wv, const float* __restrict__ bv,
    const float* __restrict__ W_out)
{
    __shared__ float sg[256], sk[256], sv[256];
    const int j = threadIdx.x;

    // lifted_graph = energy @ W_graph + b_graph  (same for all batches)
    float acc = b_graph[j];
    #pragma unroll
    for (int d = 0; d < 32; d++) acc += energy[d] * W_graph[d * 256 + j];
    sg[j] = acc;
    __syncthreads();

    // k_pre / v_pre for hetero type 2 (graph)
    float ak = bk[2 * 256 + j];
    float av = bv[2 * 256 + j];
    for (int i = 0; i < 256; i++) {
        const float gi = sg[i];
        ak += gi * Wk[2 * 65536 + i * 256 + j];
        av += gi * Wv[2 * 65536 + i * 256 + j];
    }
    sk[j] = ak;
    sv[j] = av;
    __syncthreads();

    // softmax(k) per head: warp w handles head w (32 lanes = 32 head dims)
    {
        const int w = j >> 5, lane = j & 31;
        float x = sk[w * 32 + lane];
        float m = x;
        #pragma unroll
        for (int o = 16; o > 0; o >>= 1) m = fmaxf(m, __shfl_xor_sync(0xffffffffu, m, o));
        const float e = __expf(x - m);
        float s = e;
        #pragma unroll
        for (int o = 16; o > 0; o >>= 1) s += __shfl_xor_sync(0xffffffffu, s, o);
        g_kvec[w * 32 + lane] = e / s;
    }

    // U[h][j] = sum_e v[h*32+e] * W_out[(h*32+e)][j]
    #pragma unroll
    for (int h = 0; h < 8; h++) {
        float u = 0.0f;
        #pragma unroll
        for (int e2 = 0; e2 < 32; e2++)
            u += sv[h * 32 + e2] * W_out[(h * 32 + e2) * 256 + j];
        g_U[h * 256 + j] = u;
    }

    // fused bias for first GEMM: bnq = b_node @ Wq + bq
    float bn = bq[j];
    for (int m2 = 0; m2 < 256; m2++) bn += b_node[m2] * Wq[m2 * 256 + j];
    g_bnq[j] = bn;
}

// ---------------------------------------------------------------------------
// Precompute 2: Wnq = W_node(128x256) @ Wq(256x256). Block i = output row.
// ---------------------------------------------------------------------------
__global__ void precompute2_kernel(const float* __restrict__ W_node,
                                   const float* __restrict__ Wq)
{
    __shared__ float srow[256];
    const int i = blockIdx.x;   // 0..127
    const int j = threadIdx.x;  // 0..255
    srow[j] = W_node[i * 256 + j];
    __syncthreads();
    float acc = 0.0f;
    for (int m = 0; m < 256; m++) acc += srow[m] * Wq[m * 256 + j];
    g_Wnq[i * 256 + j] = acc;
}

// ---------------------------------------------------------------------------
// Main fused kernel: per 64-row tile
//   Y = X(64x128) @ Wnq + bnq  -> per-head softmax -> q, c
//   Z = q @ W_out + c @ U + b_out
// Thread mapping: tcol = tid&31 (lane), trow = tid>>5 (warp).
// Thread owns rows {trow + 8i} and cols {tcol + 32j}  (i,j in 0..7).
// => head chunk j lives entirely across one warp's lanes -> shfl softmax.
// => Xs/Qs row reads are warp-uniform (broadcast), Ws reads conflict-free.
// ---------------------------------------------------------------------------
extern __shared__ float s_mem[];

__global__ __launch_bounds__(THREADS, 1)
void ghca_main_kernel(const float* __restrict__ X,
                      const float* __restrict__ W_out,
                      const float* __restrict__ b_out,
                      float* __restrict__ out)
{
    float* Xs  = s_mem;          //  8192 floats: X tile  [64][128]
    float* Ws  = Xs + 8192;      //  8192 floats: weight stage [32][256]
    float* Qs  = Ws + 8192;      // 16384 floats: q tile  [64][256]
    float* Us  = Qs + 16384;     //  2048 floats: U       [8][256]
    float* Cs  = Us + 2048;      //   512 floats: c       [64][8]
    float* bb  = Cs + 512;       //   256 floats: b_out
    float* kvs = bb + 256;       //   256 floats: softmaxed k
    float* bnq = kvs + 256;      //   256 floats: fused bias

    const int tid  = threadIdx.x;
    const int row0 = blockIdx.x * ROWS_PER_BLK;
    const int tcol = tid & 31;
    const int trow = tid >> 5;

    // ---- cooperative loads ----
    {
        const float4* src = (const float4*)(X + (size_t)row0 * 128);
        float4* dst = (float4*)Xs;
        #pragma unroll
        for (int t = tid; t < 2048; t += THREADS) dst[t] = src[t];
        const float4* us = (const float4*)g_U;
        float4* ud = (float4*)Us;
        #pragma unroll
        for (int t = tid; t < 512; t += THREADS) ud[t] = us[t];
        bb[tid]  = b_out[tid];
        kvs[tid] = g_kvec[tid];
        bnq[tid] = g_bnq[tid];
    }

    float acc[8][8];
    #pragma unroll
    for (int i = 0; i < 8; i++)
        #pragma unroll
        for (int j = 0; j < 8; j++) acc[i][j] = 0.0f;

    // ---- Phase 1: Y = X @ Wnq (K = 128, staged 32 rows at a time) ----
    for (int kk = 0; kk < 4; kk++) {
        __syncthreads();
        {
            const float4* wsrc = (const float4*)(g_Wnq + kk * 32 * 256);
            float4* wdst = (float4*)Ws;
            #pragma unroll
            for (int t = tid; t < 2048; t += THREADS) wdst[t] = wsrc[t];
        }
        __syncthreads();
        #pragma unroll
        for (int k2 = 0; k2 < 32; k2++) {
            const int k = kk * 32 + k2;
            float a[8], b[8];
            #pragma unroll
            for (int i = 0; i < 8; i++) a[i] = Xs[(trow + 8 * i) * 128 + k];
            #pragma unroll
            for (int j = 0; j < 8; j++) b[j] = Ws[k2 * 256 + tcol + 32 * j];
            #pragma unroll
            for (int i = 0; i < 8; i++)
                #pragma unroll
                for (int j = 0; j < 8; j++)
                    acc[i][j] = fmaf(a[i], b[j], acc[i][j]);
        }
    }

    // ---- bias + per-head softmax + c = s/max(s,1e-8) ----
    #pragma unroll
    for (int i = 0; i < 8; i++) {
        const int row = trow + 8 * i;
        #pragma unroll
        for (int j = 0; j < 8; j++) {
            const float y = acc[i][j] + bnq[tcol + 32 * j];
            float m = y;
            #pragma unroll
            for (int o = 16; o > 0; o >>= 1) m = fmaxf(m, __shfl_xor_sync(0xffffffffu, m, o));
            const float e = __expf(y - m);
            float s = e;
            #pragma unroll
            for (int o = 16; o > 0; o >>= 1) s += __shfl_xor_sync(0xffffffffu, s, o);
            const float q = e / s;
            Qs[row * 256 + tcol + 32 * j] = q;
            float p = q * kvs[32 * j + tcol];
            #pragma unroll
            for (int o = 16; o > 0; o >>= 1) p += __shfl_xor_sync(0xffffffffu, p, o);
            if (tcol == 0) Cs[row * 8 + j] = (p >= 1e-8f) ? 1.0f : p * 1e8f;
        }
    }

    // ---- Phase 2: Z = Q @ W_out (K = 256) ----
    #pragma unroll
    for (int i = 0; i < 8; i++)
        #pragma unroll
        for (int j = 0; j < 8; j++) acc[i][j] = 0.0f;

    for (int kk = 0; kk < 8; kk++) {
        __syncthreads();
        {
            const float4* wsrc = (const float4*)(W_out + kk * 32 * 256);
            float4* wdst = (float4*)Ws;
            #pragma unroll
            for (int t = tid; t < 2048; t += THREADS) wdst[t] = wsrc[t];
        }
        __syncthreads();
        #pragma unroll
        for (int k2 = 0; k2 < 32; k2++) {
            const int m = kk * 32 + k2;
            float a[8], b[8];
            #pragma unroll
            for (int i = 0; i < 8; i++) a[i] = Qs[(trow + 8 * i) * 256 + m];
            #pragma unroll
            for (int j = 0; j < 8; j++) b[j] = Ws[k2 * 256 + tcol + 32 * j];
            #pragma unroll
            for (int i = 0; i < 8; i++)
                #pragma unroll
                for (int j = 0; j < 8; j++)
                    acc[i][j] = fmaf(a[i], b[j], acc[i][j]);
        }
    }

    // ---- epilogue: + c @ U + b_out, write out ----
    #pragma unroll
    for (int i = 0; i < 8; i++) {
        const int row = trow + 8 * i;
        float c[8];
        #pragma unroll
        for (int h = 0; h < 8; h++) c[h] = Cs[row * 8 + h];
        #pragma unroll
        for (int j = 0; j < 8; j++) {
            const int col = tcol + 32 * j;
            float r = acc[i][j] + bb[col];
            #pragma unroll
            for (int h = 0; h < 8; h++) r = fmaf(c[h], Us[h * 256 + col], r);
            out[(size_t)(row0 + row) * 256 + col] = r;
        }
    }
}

// ---------------------------------------------------------------------------
// Launch. Input order (metadata): node_features, edge_features, energy,
// W_node, b_node, W_edge, b_edge, W_graph, b_graph, Wq, bq, Wk, bk, Wv, bv,
// W_out, b_out. edge_features / W_edge / b_edge are dead (loop overwrite).
// ---------------------------------------------------------------------------
extern "C" void kernel_launch(void* const* d_in, const int* in_sizes, int n_in,
                              void* d_out, int out_size)
{
    const float* node    = (const float*)d_in[0];
    const float* energy  = (const float*)d_in[2];
    const float* W_node  = (const float*)d_in[3];
    const float* b_node  = (const float*)d_in[4];
    const float* W_graph = (const float*)d_in[7];
    const float* b_graph = (const float*)d_in[8];
    const float* Wq      = (const float*)d_in[9];
    const float* bq      = (const float*)d_in[10];
    const float* Wk      = (const float*)d_in[11];
    const float* bk      = (const float*)d_in[12];
    const float* Wv      = (const float*)d_in[13];
    const float* bv      = (const float*)d_in[14];
    const float* W_out   = (const float*)d_in[15];
    const float* b_out   = (const float*)d_in[16];
    float* out = (float*)d_out;

    precompute1_kernel<<<1, 256>>>(energy, W_graph, b_graph, Wq, bq, b_node,
                                   Wk, bk, Wv, bv, W_out);
    precompute2_kernel<<<128, 256>>>(W_node, Wq);

    cudaFuncSetAttribute(ghca_main_kernel,
                         cudaFuncAttributeMaxDynamicSharedMemorySize, SMEM_BYTES);
    ghca_main_kernel<<<NROWS_TOTAL / ROWS_PER_BLK, THREADS, SMEM_BYTES>>>(
        node, W_out, b_out, out);
}